// round 1
// baseline (speedup 1.0000x reference)
#include <cuda_runtime.h>
#include <cuda_bf16.h>

#define BB 4
#define NN 2048
#define EE 2
#define DD 32
#define HH 64
#define CC 10
#define N_STEPS 5
#define CAP 128
#define ROWS (BB*NN)   // 8192

// Scratch (allocation-free): index lists, counts, double-buffered state, pooled.
__device__ unsigned short g_idx[ROWS][4][CAP];   // groups: in_e0, in_e1, out_e0, out_e1
__device__ int            g_cnt[ROWS][4];
__device__ float          g_state[2][ROWS*DD];
__device__ float          g_pooled[BB][DD];

__device__ __forceinline__ float sigmoidf_(float x) { return 1.f / (1.f + __expf(-x)); }

// ---------------------------------------------------------------------------
// Kernel 1: scan A (B,N,2*N*E) once, build per-(row,group) index lists.
// One warp per (row, group) of 2048 floats. Streaming loads (A never reused).
// ---------------------------------------------------------------------------
__global__ void build_idx_kernel(const float* __restrict__ A) {
    int wid  = (blockIdx.x * blockDim.x + threadIdx.x) >> 5;
    int lane = threadIdx.x & 31;
    if (wid >= ROWS * 4) return;
    int row = wid >> 2;
    int grp = wid & 3;
    const float4* A4 = (const float4*)(A + (size_t)row * (4 * NN) + (size_t)grp * NN);
    unsigned short* ip = g_idx[row][grp];
    int cnt = 0;
    #pragma unroll
    for (int c = 0; c < NN / 128; c++) {   // 16 iterations, 128B coalesced per lane-row
        float4 v = __ldcs(&A4[c * 32 + lane]);
        float vals[4] = {v.x, v.y, v.z, v.w};
        #pragma unroll
        for (int k = 0; k < 4; k++) {
            unsigned mask = __ballot_sync(0xFFFFFFFFu, vals[k] != 0.f);
            if (vals[k] != 0.f) {
                int pos = cnt + __popc(mask & ((1u << lane) - 1));
                if (pos < CAP)
                    ip[pos] = (unsigned short)((((c * 32 + lane) << 2) + k));
            }
            cnt += __popc(mask);
        }
    }
    if (lane == 0) g_cnt[row][grp] = cnt < CAP ? cnt : CAP;
}

// ---------------------------------------------------------------------------
// Kernel 2: one GRU step. Warp per row; lane = feature dim (D=32).
// Sparse gather-sums grouped by expert, then tiny shuffle-broadcast matmuls.
// ---------------------------------------------------------------------------
__global__ void step_kernel(const float* __restrict__ src, float* __restrict__ dst,
                            const float* __restrict__ W_in,  const float* __restrict__ b_in,
                            const float* __restrict__ W_out, const float* __restrict__ b_out,
                            const float* __restrict__ Wr, const float* __restrict__ br,
                            const float* __restrict__ Wz, const float* __restrict__ bz,
                            const float* __restrict__ Wh, const float* __restrict__ bh) {
    int wid  = (blockIdx.x * blockDim.x + threadIdx.x) >> 5;
    int lane = threadIdx.x & 31;
    if (wid >= ROWS) return;
    int row = wid;
    const float* sb = src + (size_t)(row & ~(NN - 1)) * DD;   // batch base

    float s[4]; float c[4];
    #pragma unroll
    for (int g = 0; g < 4; g++) {
        int cnt = g_cnt[row][g];
        const unsigned short* ip = g_idx[row][g];
        float acc = 0.f;
        #pragma unroll 4
        for (int i = 0; i < cnt; i++) {
            int m = ip[i];                 // warp-uniform broadcast load
            acc += sb[m * DD + lane];      // 128B coalesced gather
        }
        s[g] = acc;
        c[g] = (float)cnt;
    }

    // Expert transforms: a_in = s0@Win0 + s1@Win1 + cnt*b ; a_out likewise
    float a_in  = c[0] * b_in[lane]  + c[1] * b_in[DD + lane];
    float a_out = c[2] * b_out[lane] + c[3] * b_out[DD + lane];
    #pragma unroll
    for (int d = 0; d < DD; d++) {
        a_in  += __shfl_sync(0xFFFFFFFFu, s[0], d) * W_in[d * DD + lane]
               + __shfl_sync(0xFFFFFFFFu, s[1], d) * W_in[DD * DD + d * DD + lane];
        a_out += __shfl_sync(0xFFFFFFFFu, s[2], d) * W_out[d * DD + lane]
               + __shfl_sync(0xFFFFFFFFu, s[3], d) * W_out[DD * DD + d * DD + lane];
    }

    float st = src[(size_t)row * DD + lane];

    // r,z gates: a = [a_in, a_out, st] (96) @ Wr/Wz (96x32)
    float rr = br[lane], zz = bz[lane];
    #pragma unroll
    for (int d = 0; d < DD; d++) {
        float ai = __shfl_sync(0xFFFFFFFFu, a_in,  d);
        float ao = __shfl_sync(0xFFFFFFFFu, a_out, d);
        float ss = __shfl_sync(0xFFFFFFFFu, st,    d);
        rr += ai * Wr[d * DD + lane] + ao * Wr[(DD + d) * DD + lane] + ss * Wr[(2 * DD + d) * DD + lane];
        zz += ai * Wz[d * DD + lane] + ao * Wz[(DD + d) * DD + lane] + ss * Wz[(2 * DD + d) * DD + lane];
    }
    rr = sigmoidf_(rr);
    zz = sigmoidf_(zz);
    float rs = rr * st;

    // candidate: joined = [a_in, a_out, r*st] @ Wh
    float hh = bh[lane];
    #pragma unroll
    for (int d = 0; d < DD; d++) {
        hh += __shfl_sync(0xFFFFFFFFu, a_in,  d) * Wh[d * DD + lane]
            + __shfl_sync(0xFFFFFFFFu, a_out, d) * Wh[(DD + d) * DD + lane]
            + __shfl_sync(0xFFFFFFFFu, rs,    d) * Wh[(2 * DD + d) * DD + lane];
    }
    hh = tanhf(hh);

    dst[(size_t)row * DD + lane] = (1.f - zz) * st + zz * hh;
}

// ---------------------------------------------------------------------------
// Kernel 3: attention pooling per batch. One block per b, 8 warps.
// ---------------------------------------------------------------------------
__global__ void pool_kernel(const float* __restrict__ state,
                            const float* __restrict__ Wa1, const float* __restrict__ ba1,
                            const float* __restrict__ Wa2, const float* __restrict__ ba2) {
    int b    = blockIdx.x;
    int lane = threadIdx.x & 31;
    int warp = threadIdx.x >> 5;   // 0..7
    __shared__ float pooled_s[DD];
    if (threadIdx.x < DD) pooled_s[threadIdx.x] = 0.f;
    __syncthreads();

    float accp = 0.f;
    for (int n = warp; n < NN; n += 8) {
        const float* strow = state + ((size_t)b * NN + n) * DD;
        float sv = strow[lane];
        float t = ba1[lane];
        #pragma unroll
        for (int d = 0; d < DD; d++)
            t += __shfl_sync(0xFFFFFFFFu, sv, d) * Wa1[d * DD + lane];
        t = t > 0.f ? t : 0.01f * t;            // leaky
        float p = t * Wa2[lane];
        #pragma unroll
        for (int o = 16; o > 0; o >>= 1)
            p += __shfl_xor_sync(0xFFFFFFFFu, p, o);
        float att = sigmoidf_(p + ba2[0]);
        accp += sv * att;
    }
    atomicAdd(&pooled_s[lane], accp);
    __syncthreads();
    if (threadIdx.x < DD) g_pooled[b][threadIdx.x] = pooled_s[threadIdx.x];
}

// ---------------------------------------------------------------------------
// Kernel 4: classifier + softmax. Single block.
// ---------------------------------------------------------------------------
__global__ void cls_kernel(float* __restrict__ out,
                           const float* __restrict__ Wc1, const float* __restrict__ bc1,
                           const float* __restrict__ Wc2, const float* __restrict__ bc2) {
    __shared__ float hsm[BB][HH];
    __shared__ float lg[BB][CC];
    int t = threadIdx.x;   // 256
    if (t < BB * HH) {
        int b = t / HH, h = t % HH;
        float v = bc1[h];
        #pragma unroll
        for (int d = 0; d < DD; d++) v += g_pooled[b][d] * Wc1[d * HH + h];
        v = v > 0.f ? v : 0.01f * v;
        hsm[b][h] = v;
    }
    __syncthreads();
    if (t < BB * CC) {
        int b = t / CC, ci = t % CC;
        float v = bc2[ci];
        #pragma unroll
        for (int h = 0; h < HH; h++) v += hsm[b][h] * Wc2[h * CC + ci];
        lg[b][ci] = v;
    }
    __syncthreads();
    if (t < BB) {
        int b = t;
        float mx = -1e30f;
        #pragma unroll
        for (int i = 0; i < CC; i++) mx = fmaxf(mx, lg[b][i]);
        float sum = 0.f, e[CC];
        #pragma unroll
        for (int i = 0; i < CC; i++) { e[i] = expf(lg[b][i] - mx); sum += e[i]; }
        float inv = 1.f / sum;
        #pragma unroll
        for (int i = 0; i < CC; i++) out[b * CC + i] = e[i] * inv;
    }
}

// ---------------------------------------------------------------------------
extern "C" void kernel_launch(void* const* d_in, const int* in_sizes, int n_in,
                              void* d_out, int out_size) {
    const float* prop  = (const float*)d_in[0];
    const float* A     = (const float*)d_in[1];
    const float* W_in  = (const float*)d_in[2];
    const float* b_in  = (const float*)d_in[3];
    const float* W_out = (const float*)d_in[4];
    const float* b_out = (const float*)d_in[5];
    const float* Wr    = (const float*)d_in[6];
    const float* br    = (const float*)d_in[7];
    const float* Wz    = (const float*)d_in[8];
    const float* bz    = (const float*)d_in[9];
    const float* Wh    = (const float*)d_in[10];
    const float* bh    = (const float*)d_in[11];
    const float* Wa1   = (const float*)d_in[12];
    const float* ba1   = (const float*)d_in[13];
    const float* Wa2   = (const float*)d_in[14];
    const float* ba2   = (const float*)d_in[15];
    const float* Wc1   = (const float*)d_in[16];
    const float* bc1   = (const float*)d_in[17];
    const float* Wc2   = (const float*)d_in[18];
    const float* bc2   = (const float*)d_in[19];

    float* gs = nullptr;
    cudaGetSymbolAddress((void**)&gs, g_state);
    float* buf0 = gs;
    float* buf1 = gs + ROWS * DD;

    // 1) Build sparse index lists from A (one streaming pass).
    build_idx_kernel<<<(ROWS * 4) / 8, 256>>>(A);

    // 2) 5 GRU steps, double-buffered state.
    const float* src = prop;
    float* dst = buf0;
    for (int s = 0; s < N_STEPS; s++) {
        step_kernel<<<ROWS / 8, 256>>>(src, dst, W_in, b_in, W_out, b_out,
                                       Wr, br, Wz, bz, Wh, bh);
        src = dst;
        dst = (dst == buf0) ? buf1 : buf0;
    }

    // 3) Attention pooling per batch.
    pool_kernel<<<BB, 256>>>(src, Wa1, ba1, Wa2, ba2);

    // 4) Classifier head + softmax.
    cls_kernel<<<1, 256>>>((float*)d_out, Wc1, bc1, Wc2, bc2);
}

// round 2
// speedup vs baseline: 1.0057x; 1.0057x over previous
#include <cuda_runtime.h>
#include <cuda_bf16.h>

#define BB 4
#define NN 2048
#define EE 2
#define DD 32
#define HH 64
#define CC 10
#define N_STEPS 5
#define CAP 128
#define ROWS (BB*NN)   // 8192

// Scratch (allocation-free): index lists, counts, double-buffered state, pooled.
__device__ unsigned short g_idx[ROWS][4][CAP];   // groups: in_e0, in_e1, out_e0, out_e1
__device__ int            g_cnt[ROWS][4];
__device__ float          g_state[2][ROWS*DD];
__device__ float          g_pooled[BB][DD];

__device__ __forceinline__ float sigmoidf_(float x) { return 1.f / (1.f + __expf(-x)); }

// ---------------------------------------------------------------------------
// Kernel 1: scan A (B,N,2*N*E) once, build per-(row,group) index lists.
// One warp per (row, group) of 2048 floats. Streaming loads (A never reused).
// ---------------------------------------------------------------------------
__global__ void build_idx_kernel(const float* __restrict__ A) {
    int wid  = (blockIdx.x * blockDim.x + threadIdx.x) >> 5;
    int lane = threadIdx.x & 31;
    if (wid >= ROWS * 4) return;
    int row = wid >> 2;
    int grp = wid & 3;
    const float4* A4 = (const float4*)(A + (size_t)row * (4 * NN) + (size_t)grp * NN);
    unsigned short* ip = g_idx[row][grp];
    int cnt = 0;
    #pragma unroll
    for (int c = 0; c < NN / 128; c++) {   // 16 iterations, 128B coalesced per lane-row
        float4 v = __ldcs(&A4[c * 32 + lane]);
        float vals[4] = {v.x, v.y, v.z, v.w};
        #pragma unroll
        for (int k = 0; k < 4; k++) {
            unsigned mask = __ballot_sync(0xFFFFFFFFu, vals[k] != 0.f);
            if (vals[k] != 0.f) {
                int pos = cnt + __popc(mask & ((1u << lane) - 1));
                if (pos < CAP)
                    ip[pos] = (unsigned short)((((c * 32 + lane) << 2) + k));
            }
            cnt += __popc(mask);
        }
    }
    if (lane == 0) g_cnt[row][grp] = cnt < CAP ? cnt : CAP;
}

// ---------------------------------------------------------------------------
// Kernel 2: one GRU step. Warp per row; lane = feature dim (D=32).
// Sparse gather-sums grouped by expert, then tiny shuffle-broadcast matmuls.
// ---------------------------------------------------------------------------
__global__ void step_kernel(const float* __restrict__ src, float* __restrict__ dst,
                            const float* __restrict__ W_in,  const float* __restrict__ b_in,
                            const float* __restrict__ W_out, const float* __restrict__ b_out,
                            const float* __restrict__ Wr, const float* __restrict__ br,
                            const float* __restrict__ Wz, const float* __restrict__ bz,
                            const float* __restrict__ Wh, const float* __restrict__ bh) {
    int wid  = (blockIdx.x * blockDim.x + threadIdx.x) >> 5;
    int lane = threadIdx.x & 31;
    if (wid >= ROWS) return;
    int row = wid;
    const float* sb = src + (size_t)(row & ~(NN - 1)) * DD;   // batch base

    float s[4]; float c[4];
    #pragma unroll
    for (int g = 0; g < 4; g++) {
        int cnt = g_cnt[row][g];
        const unsigned short* ip = g_idx[row][g];
        float acc = 0.f;
        #pragma unroll 4
        for (int i = 0; i < cnt; i++) {
            int m = ip[i];                 // warp-uniform broadcast load
            acc += sb[m * DD + lane];      // 128B coalesced gather
        }
        s[g] = acc;
        c[g] = (float)cnt;
    }

    // Expert transforms: a_in = s0@Win0 + s1@Win1 + cnt*b ; a_out likewise
    float a_in  = c[0] * b_in[lane]  + c[1] * b_in[DD + lane];
    float a_out = c[2] * b_out[lane] + c[3] * b_out[DD + lane];
    #pragma unroll
    for (int d = 0; d < DD; d++) {
        a_in  += __shfl_sync(0xFFFFFFFFu, s[0], d) * W_in[d * DD + lane]
               + __shfl_sync(0xFFFFFFFFu, s[1], d) * W_in[DD * DD + d * DD + lane];
        a_out += __shfl_sync(0xFFFFFFFFu, s[2], d) * W_out[d * DD + lane]
               + __shfl_sync(0xFFFFFFFFu, s[3], d) * W_out[DD * DD + d * DD + lane];
    }

    float st = src[(size_t)row * DD + lane];

    // r,z gates: a = [a_in, a_out, st] (96) @ Wr/Wz (96x32)
    float rr = br[lane], zz = bz[lane];
    #pragma unroll
    for (int d = 0; d < DD; d++) {
        float ai = __shfl_sync(0xFFFFFFFFu, a_in,  d);
        float ao = __shfl_sync(0xFFFFFFFFu, a_out, d);
        float ss = __shfl_sync(0xFFFFFFFFu, st,    d);
        rr += ai * Wr[d * DD + lane] + ao * Wr[(DD + d) * DD + lane] + ss * Wr[(2 * DD + d) * DD + lane];
        zz += ai * Wz[d * DD + lane] + ao * Wz[(DD + d) * DD + lane] + ss * Wz[(2 * DD + d) * DD + lane];
    }
    rr = sigmoidf_(rr);
    zz = sigmoidf_(zz);
    float rs = rr * st;

    // candidate: joined = [a_in, a_out, r*st] @ Wh
    float hh = bh[lane];
    #pragma unroll
    for (int d = 0; d < DD; d++) {
        hh += __shfl_sync(0xFFFFFFFFu, a_in,  d) * Wh[d * DD + lane]
            + __shfl_sync(0xFFFFFFFFu, a_out, d) * Wh[(DD + d) * DD + lane]
            + __shfl_sync(0xFFFFFFFFu, rs,    d) * Wh[(2 * DD + d) * DD + lane];
    }
    hh = tanhf(hh);

    dst[(size_t)row * DD + lane] = (1.f - zz) * st + zz * hh;
}

// ---------------------------------------------------------------------------
// Kernel 3: attention pooling per batch. One block per b, 8 warps.
// ---------------------------------------------------------------------------
__global__ void pool_kernel(const float* __restrict__ state,
                            const float* __restrict__ Wa1, const float* __restrict__ ba1,
                            const float* __restrict__ Wa2, const float* __restrict__ ba2) {
    int b    = blockIdx.x;
    int lane = threadIdx.x & 31;
    int warp = threadIdx.x >> 5;   // 0..7
    __shared__ float pooled_s[DD];
    if (threadIdx.x < DD) pooled_s[threadIdx.x] = 0.f;
    __syncthreads();

    float accp = 0.f;
    for (int n = warp; n < NN; n += 8) {
        const float* strow = state + ((size_t)b * NN + n) * DD;
        float sv = strow[lane];
        float t = ba1[lane];
        #pragma unroll
        for (int d = 0; d < DD; d++)
            t += __shfl_sync(0xFFFFFFFFu, sv, d) * Wa1[d * DD + lane];
        t = t > 0.f ? t : 0.01f * t;            // leaky
        float p = t * Wa2[lane];
        #pragma unroll
        for (int o = 16; o > 0; o >>= 1)
            p += __shfl_xor_sync(0xFFFFFFFFu, p, o);
        float att = sigmoidf_(p + ba2[0]);
        accp += sv * att;
    }
    atomicAdd(&pooled_s[lane], accp);
    __syncthreads();
    if (threadIdx.x < DD) g_pooled[b][threadIdx.x] = pooled_s[threadIdx.x];
}

// ---------------------------------------------------------------------------
// Kernel 4: classifier + softmax. Single block.
// ---------------------------------------------------------------------------
__global__ void cls_kernel(float* __restrict__ out,
                           const float* __restrict__ Wc1, const float* __restrict__ bc1,
                           const float* __restrict__ Wc2, const float* __restrict__ bc2) {
    __shared__ float hsm[BB][HH];
    __shared__ float lg[BB][CC];
    int t = threadIdx.x;   // 256
    if (t < BB * HH) {
        int b = t / HH, h = t % HH;
        float v = bc1[h];
        #pragma unroll
        for (int d = 0; d < DD; d++) v += g_pooled[b][d] * Wc1[d * HH + h];
        v = v > 0.f ? v : 0.01f * v;
        hsm[b][h] = v;
    }
    __syncthreads();
    if (t < BB * CC) {
        int b = t / CC, ci = t % CC;
        float v = bc2[ci];
        #pragma unroll
        for (int h = 0; h < HH; h++) v += hsm[b][h] * Wc2[h * CC + ci];
        lg[b][ci] = v;
    }
    __syncthreads();
    if (t < BB) {
        int b = t;
        float mx = -1e30f;
        #pragma unroll
        for (int i = 0; i < CC; i++) mx = fmaxf(mx, lg[b][i]);
        float sum = 0.f, e[CC];
        #pragma unroll
        for (int i = 0; i < CC; i++) { e[i] = expf(lg[b][i] - mx); sum += e[i]; }
        float inv = 1.f / sum;
        #pragma unroll
        for (int i = 0; i < CC; i++) out[b * CC + i] = e[i] * inv;
    }
}

// ---------------------------------------------------------------------------
extern "C" void kernel_launch(void* const* d_in, const int* in_sizes, int n_in,
                              void* d_out, int out_size) {
    const float* prop  = (const float*)d_in[0];
    const float* A     = (const float*)d_in[1];
    const float* W_in  = (const float*)d_in[2];
    const float* b_in  = (const float*)d_in[3];
    const float* W_out = (const float*)d_in[4];
    const float* b_out = (const float*)d_in[5];
    const float* Wr    = (const float*)d_in[6];
    const float* br    = (const float*)d_in[7];
    const float* Wz    = (const float*)d_in[8];
    const float* bz    = (const float*)d_in[9];
    const float* Wh    = (const float*)d_in[10];
    const float* bh    = (const float*)d_in[11];
    const float* Wa1   = (const float*)d_in[12];
    const float* ba1   = (const float*)d_in[13];
    const float* Wa2   = (const float*)d_in[14];
    const float* ba2   = (const float*)d_in[15];
    const float* Wc1   = (const float*)d_in[16];
    const float* bc1   = (const float*)d_in[17];
    const float* Wc2   = (const float*)d_in[18];
    const float* bc2   = (const float*)d_in[19];

    float* gs = nullptr;
    cudaGetSymbolAddress((void**)&gs, g_state);
    float* buf0 = gs;
    float* buf1 = gs + ROWS * DD;

    // 1) Build sparse index lists from A (one streaming pass).
    build_idx_kernel<<<(ROWS * 4) / 8, 256>>>(A);

    // 2) 5 GRU steps, double-buffered state.
    const float* src = prop;
    float* dst = buf0;
    for (int s = 0; s < N_STEPS; s++) {
        step_kernel<<<ROWS / 8, 256>>>(src, dst, W_in, b_in, W_out, b_out,
                                       Wr, br, Wz, bz, Wh, bh);
        src = dst;
        dst = (dst == buf0) ? buf1 : buf0;
    }

    // 3) Attention pooling per batch.
    pool_kernel<<<BB, 256>>>(src, Wa1, ba1, Wa2, ba2);

    // 4) Classifier head + softmax.
    cls_kernel<<<1, 256>>>((float*)d_out, Wc1, bc1, Wc2, bc2);
}